// round 3
// baseline (speedup 1.0000x reference)
#include <cuda_runtime.h>
#include <cstdint>
#include <math.h>

// ----------------------------------------------------------------------------
// Problem constants
// ----------------------------------------------------------------------------
#define M_ROWS 20000
#define K_DIM  9480
#define N_DIM  128
// groups/experts
#define NG 8
#define NE 16

// Scratch for router output h [M, 128]  (10.24 MB, device global = allowed)
__device__ float g_h[M_ROWS * N_DIM];

// ----------------------------------------------------------------------------
// tf32 helpers
// ----------------------------------------------------------------------------
__device__ __forceinline__ uint32_t f2tf32(float a) {
  uint32_t r;
  asm("cvt.rna.tf32.f32 %0, %1;" : "=r"(r) : "f"(a));
  return r;
}

#define MMA_TF32(d, a, b)                                                      \
  asm volatile(                                                                \
      "mma.sync.aligned.m16n8k8.row.col.f32.tf32.tf32.f32 "                    \
      "{%0,%1,%2,%3}, {%4,%5,%6,%7}, {%8,%9}, {%0,%1,%2,%3};"                  \
      : "+f"(d[0]), "+f"(d[1]), "+f"(d[2]), "+f"(d[3])                         \
      : "r"(a[0]), "r"(a[1]), "r"(a[2]), "r"(a[3]), "r"(b[0]), "r"(b[1]))

// ----------------------------------------------------------------------------
// Router GEMM: h = x[M,K] @ Wr[K,N] + br, computed with 3xTF32 (fp32-accurate)
// CTA tile 128x128xBK16, 8 warps (4x2), warp tile 32x64 (2x8 m16n8 frags)
// ----------------------------------------------------------------------------
__global__ __launch_bounds__(256) void router_gemm(
    const float* __restrict__ x, const float* __restrict__ Wr,
    const float* __restrict__ br) {
  // padded smem: A stride 20 (frag loads conflict-free), B stride 136
  __shared__ __align__(16) float As_h[128][20];
  __shared__ __align__(16) float As_l[128][20];
  __shared__ __align__(16) float Bs_h[16][136];
  __shared__ __align__(16) float Bs_l[16][136];

  const int tid   = threadIdx.x;
  const int lane  = tid & 31;
  const int wid   = tid >> 5;
  const int warpM = wid & 3;   // 4 warps along M (32 rows each)
  const int warpN = wid >> 2;  // 2 warps along N (64 cols each)
  const int m0    = blockIdx.x * 128;
  const int g     = lane >> 2;  // groupID
  const int tg    = lane & 3;   // thread-in-group

  float acc[2][8][4];
#pragma unroll
  for (int mf = 0; mf < 2; ++mf)
#pragma unroll
    for (int nf = 0; nf < 8; ++nf)
#pragma unroll
      for (int j = 0; j < 4; ++j) acc[mf][nf][j] = 0.0f;

  const int ktiles = (K_DIM + 15) / 16;  // 593 (last tile has 8 valid k)

  for (int kt = 0; kt < ktiles; ++kt) {
    const int k0 = kt * 16;

    // ---- load A tile (128x16 fp32), split into tf32 hi/lo ----
#pragma unroll
    for (int i = 0; i < 2; ++i) {
      int q   = tid + i * 256;     // 0..511 float4 slots
      int row = q >> 2;            // 0..127
      int k4  = (q & 3) * 4;       // 0,4,8,12
      int gr  = m0 + row;
      int gk  = k0 + k4;
      float4 v = make_float4(0.f, 0.f, 0.f, 0.f);
      if (gr < M_ROWS && gk + 3 < K_DIM)
        v = *(const float4*)(x + (size_t)gr * K_DIM + gk);
      float h0 = __uint_as_float(f2tf32(v.x));
      float h1 = __uint_as_float(f2tf32(v.y));
      float h2 = __uint_as_float(f2tf32(v.z));
      float h3 = __uint_as_float(f2tf32(v.w));
      As_h[row][k4 + 0] = h0;
      As_h[row][k4 + 1] = h1;
      As_h[row][k4 + 2] = h2;
      As_h[row][k4 + 3] = h3;
      As_l[row][k4 + 0] = __uint_as_float(f2tf32(v.x - h0));
      As_l[row][k4 + 1] = __uint_as_float(f2tf32(v.y - h1));
      As_l[row][k4 + 2] = __uint_as_float(f2tf32(v.z - h2));
      As_l[row][k4 + 3] = __uint_as_float(f2tf32(v.w - h3));
    }

    // ---- load B tile (16x128 fp32), split into tf32 hi/lo ----
#pragma unroll
    for (int i = 0; i < 2; ++i) {
      int q  = tid + i * 256;  // 0..511 float4 slots
      int kr = q >> 5;         // 0..15
      int n4 = (q & 31) * 4;   // 0..124
      int gk = k0 + kr;
      float4 v = make_float4(0.f, 0.f, 0.f, 0.f);
      if (gk < K_DIM) v = *(const float4*)(Wr + (size_t)gk * N_DIM + n4);
      float h0 = __uint_as_float(f2tf32(v.x));
      float h1 = __uint_as_float(f2tf32(v.y));
      float h2 = __uint_as_float(f2tf32(v.z));
      float h3 = __uint_as_float(f2tf32(v.w));
      Bs_h[kr][n4 + 0] = h0;
      Bs_h[kr][n4 + 1] = h1;
      Bs_h[kr][n4 + 2] = h2;
      Bs_h[kr][n4 + 3] = h3;
      Bs_l[kr][n4 + 0] = __uint_as_float(f2tf32(v.x - h0));
      Bs_l[kr][n4 + 1] = __uint_as_float(f2tf32(v.y - h1));
      Bs_l[kr][n4 + 2] = __uint_as_float(f2tf32(v.z - h2));
      Bs_l[kr][n4 + 3] = __uint_as_float(f2tf32(v.w - h3));
    }
    __syncthreads();

    // ---- compute: 2 k8 steps ----
#pragma unroll
    for (int kk = 0; kk < 2; ++kk) {
      const int kb = kk * 8;
      uint32_t ah[2][4], al[2][4];
#pragma unroll
      for (int mf = 0; mf < 2; ++mf) {
        const int r = warpM * 32 + mf * 16;
        ah[mf][0] = __float_as_uint(As_h[r + g][kb + tg]);
        ah[mf][1] = __float_as_uint(As_h[r + g + 8][kb + tg]);
        ah[mf][2] = __float_as_uint(As_h[r + g][kb + tg + 4]);
        ah[mf][3] = __float_as_uint(As_h[r + g + 8][kb + tg + 4]);
        al[mf][0] = __float_as_uint(As_l[r + g][kb + tg]);
        al[mf][1] = __float_as_uint(As_l[r + g + 8][kb + tg]);
        al[mf][2] = __float_as_uint(As_l[r + g][kb + tg + 4]);
        al[mf][3] = __float_as_uint(As_l[r + g + 8][kb + tg + 4]);
      }
      uint32_t bh[8][2], bl[8][2];
#pragma unroll
      for (int nf = 0; nf < 8; ++nf) {
        const int c = warpN * 64 + nf * 8 + g;
        bh[nf][0] = __float_as_uint(Bs_h[kb + tg][c]);
        bh[nf][1] = __float_as_uint(Bs_h[kb + tg + 4][c]);
        bl[nf][0] = __float_as_uint(Bs_l[kb + tg][c]);
        bl[nf][1] = __float_as_uint(Bs_l[kb + tg + 4][c]);
      }
#pragma unroll
      for (int mf = 0; mf < 2; ++mf)
#pragma unroll
        for (int nf = 0; nf < 8; ++nf) {
          MMA_TF32(acc[mf][nf], ah[mf], bh[nf]);  // hi*hi
          MMA_TF32(acc[mf][nf], ah[mf], bl[nf]);  // hi*lo
          MMA_TF32(acc[mf][nf], al[mf], bh[nf]);  // lo*hi
        }
    }
    __syncthreads();
  }

  // ---- store h (+ bias) ----
#pragma unroll
  for (int mf = 0; mf < 2; ++mf) {
#pragma unroll
    for (int nf = 0; nf < 8; ++nf) {
      const int r0 = m0 + warpM * 32 + mf * 16 + g;
      const int c0 = warpN * 64 + nf * 8 + tg * 2;
      if (r0 < M_ROWS) {
        g_h[(size_t)r0 * N_DIM + c0]     = acc[mf][nf][0] + br[c0];
        g_h[(size_t)r0 * N_DIM + c0 + 1] = acc[mf][nf][1] + br[c0 + 1];
      }
      if (r0 + 8 < M_ROWS) {
        g_h[(size_t)(r0 + 8) * N_DIM + c0]     = acc[mf][nf][2] + br[c0];
        g_h[(size_t)(r0 + 8) * N_DIM + c0 + 1] = acc[mf][nf][3] + br[c0 + 1];
      }
    }
  }
}

// ----------------------------------------------------------------------------
// Epilogue: one warp per sample. top-2 gating -> experts (selected groups only)
// -> QKV -> 4x4 attention -> Wo at the selected expert -> weighted sum.
// ----------------------------------------------------------------------------
__global__ __launch_bounds__(256) void moe_epilogue(
    const float* __restrict__ We, const float* __restrict__ be,
    const float* __restrict__ Wq, const float* __restrict__ bq,
    const float* __restrict__ Wk, const float* __restrict__ bk,
    const float* __restrict__ Wv, const float* __restrict__ bvp,
    const float* __restrict__ Wo, const float* __restrict__ bo,
    float* __restrict__ out) {
  const int tid  = threadIdx.x;
  const int lane = tid & 31;
  const int w    = tid >> 5;
  const int n    = blockIdx.x * 8 + w;  // grid sized so n < M_ROWS always

  __shared__ __align__(16) float h_s[8][128];
  __shared__ float eo_s[8][32];
  __shared__ float qs[8][32];
  __shared__ float ks[8][32];
  __shared__ float vs[8][32];
  __shared__ float att_s[8][32];

  // 1) load h row, find top-2 (value desc, index asc on ties)
  float4 hv = *(const float4*)(g_h + (size_t)n * N_DIM + lane * 4);
  *(float4*)(&h_s[w][lane * 4]) = hv;
  float vals[4] = {hv.x, hv.y, hv.z, hv.w};

  float tv = vals[0];
  int   ti = lane * 4;
#pragma unroll
  for (int j = 1; j < 4; ++j)
    if (vals[j] > tv) { tv = vals[j]; ti = lane * 4 + j; }
#pragma unroll
  for (int off = 16; off > 0; off >>= 1) {
    float ov = __shfl_down_sync(0xffffffffu, tv, off);
    int   oi = __shfl_down_sync(0xffffffffu, ti, off);
    if (ov > tv || (ov == tv && oi < ti)) { tv = ov; ti = oi; }
  }
  const float v1 = __shfl_sync(0xffffffffu, tv, 0);
  const int   i1 = __shfl_sync(0xffffffffu, ti, 0);

  tv = -INFINITY;
  ti = 1 << 30;
#pragma unroll
  for (int j = 0; j < 4; ++j) {
    int idx = lane * 4 + j;
    if (idx != i1 && (vals[j] > tv || (vals[j] == tv && idx < ti))) {
      tv = vals[j];
      ti = idx;
    }
  }
#pragma unroll
  for (int off = 16; off > 0; off >>= 1) {
    float ov = __shfl_down_sync(0xffffffffu, tv, off);
    int   oi = __shfl_down_sync(0xffffffffu, ti, off);
    if (ov > tv || (ov == tv && oi < ti)) { tv = ov; ti = oi; }
  }
  const float v2 = __shfl_sync(0xffffffffu, tv, 0);
  const int   i2 = __shfl_sync(0xffffffffu, ti, 0);

  // gating weights (softmax over the 2 selected logits)
  const float e2w = expf(v2 - v1);
  const float rw1 = 1.0f / (1.0f + e2w);
  const float rw2 = 1.0f - rw1;

  const int g0 = i1 >> 4, f0 = i1 & 15;
  const int g1 = i2 >> 4, f1 = i2 & 15;

  __syncwarp();

  // 2) expert outputs for the (up to) 2 selected groups
  {
    const int sel = lane >> 4;
    const int e   = lane & 15;
    const int gg  = sel ? g1 : g0;
    const float* wrow = We + (size_t)(gg * NE + e) * 128;
    float acc = be[gg * NE + e];
#pragma unroll 8
    for (int k4 = 0; k4 < 32; ++k4) {
      float4 wv = ((const float4*)wrow)[k4];
      const float* hp = &h_s[w][k4 * 4];
      acc += hp[0] * wv.x + hp[1] * wv.y + hp[2] * wv.z + hp[3] * wv.w;
    }
    eo_s[w][lane] = acc;
  }
  __syncwarp();

  // 3) Q/K/V projections (per-group Linear(E->E), torch [out,in] layout)
  {
    const int sel = lane >> 4;
    const int f   = lane & 15;
    const int gg  = sel ? g1 : g0;
    const float* wq = Wq + (size_t)(gg * NE + f) * NE;
    const float* wk = Wk + (size_t)(gg * NE + f) * NE;
    const float* wv_ = Wv + (size_t)(gg * NE + f) * NE;
    float qa = bq[gg * NE + f];
    float ka = bk[gg * NE + f];
    float va = bvp[gg * NE + f];
#pragma unroll
    for (int e = 0; e < 16; ++e) {
      float eov = eo_s[w][sel * 16 + e];
      qa += eov * wq[e];
      ka += eov * wk[e];
      va += eov * wv_[e];
    }
    qs[w][lane] = qa;
    ks[w][lane] = ka;
    vs[w][lane] = va;
  }
  __syncwarp();

  // 4) 4x4 attention per selected group (head_dim axis is the seq axis)
  if (lane < 8) {
    const int sel  = lane >> 2;
    const int d    = lane & 3;
    const int base = sel * 16;
    float qv[4];
#pragma unroll
    for (int hh = 0; hh < 4; ++hh) qv[hh] = qs[w][base + hh * 4 + d];
    float sc[4];
#pragma unroll
    for (int e = 0; e < 4; ++e) {
      float s = 0.0f;
#pragma unroll
      for (int hh = 0; hh < 4; ++hh) s += qv[hh] * ks[w][base + hh * 4 + e];
      sc[e] = s * 0.5f;  // / sqrt(DH=4)
    }
    float mx = fmaxf(fmaxf(sc[0], sc[1]), fmaxf(sc[2], sc[3]));
    float ex[4], ssum = 0.0f;
#pragma unroll
    for (int e = 0; e < 4; ++e) {
      ex[e] = expf(sc[e] - mx);
      ssum += ex[e];
    }
    const float inv = 1.0f / ssum;
#pragma unroll
    for (int hh = 0; hh < 4; ++hh) {
      float a = 0.0f;
#pragma unroll
      for (int e = 0; e < 4; ++e) a += ex[e] * inv * vs[w][base + hh * 4 + e];
      att_s[w][base + hh * 4 + d] = a;  // att_flat[g, hh*4+d]
    }
  }
  __syncwarp();

  // 5) output projection at the selected expert index + gated combine
  {
    const int sel = lane & 1;
    const int gg  = sel ? g1 : g0;
    const int f   = sel ? f1 : f0;
    const float* wo = Wo + (size_t)(gg * NE + f) * NE;
    float o = bo[gg * NE + f];
#pragma unroll
    for (int e = 0; e < 16; ++e) o += att_s[w][sel * 16 + e] * wo[e];
    const float o0 = __shfl_sync(0xffffffffu, o, 0);
    const float o1 = __shfl_sync(0xffffffffu, o, 1);
    if (lane == 0) out[n] = rw1 * o0 + rw2 * o1;
  }
}

// ----------------------------------------------------------------------------
// launch
// ----------------------------------------------------------------------------
extern "C" void kernel_launch(void* const* d_in, const int* in_sizes, int n_in,
                              void* d_out, int out_size) {
  const float* x  = (const float*)d_in[0];
  const float* Wr = (const float*)d_in[1];
  const float* br = (const float*)d_in[2];
  const float* We = (const float*)d_in[3];
  const float* be = (const float*)d_in[4];
  const float* Wq = (const float*)d_in[5];
  const float* bq = (const float*)d_in[6];
  const float* Wk = (const float*)d_in[7];
  const float* bk = (const float*)d_in[8];
  const float* Wv = (const float*)d_in[9];
  const float* bv = (const float*)d_in[10];
  const float* Wo = (const float*)d_in[11];
  const float* bo = (const float*)d_in[12];
  float* out = (float*)d_out;

  router_gemm<<<(M_ROWS + 127) / 128, 256>>>(x, Wr, br);
  moe_epilogue<<<M_ROWS / 8, 256>>>(We, be, Wq, bq, Wk, bk, Wv, bv, Wo, bo,
                                    out);
}

// round 4
// speedup vs baseline: 1.0057x; 1.0057x over previous
#include <cuda_runtime.h>
#include <cstdint>
#include <math.h>

// ----------------------------------------------------------------------------
// Problem constants
// ----------------------------------------------------------------------------
#define M_ROWS 20000
#define K_DIM  9480
#define N_DIM  128
// groups/experts
#define NG 8
#define NE 16

// Scratch for router output h [M, 128]  (10.24 MB, device global = allowed)
__device__ float g_h[M_ROWS * N_DIM];

// ----------------------------------------------------------------------------
// tf32 helpers
// ----------------------------------------------------------------------------
__device__ __forceinline__ uint32_t f2tf32(float a) {
  uint32_t r;
  asm("cvt.rna.tf32.f32 %0, %1;" : "=r"(r) : "f"(a));
  return r;
}

#define MMA_TF32(d, a, b)                                                      \
  asm volatile(                                                                \
      "mma.sync.aligned.m16n8k8.row.col.f32.tf32.tf32.f32 "                    \
      "{%0,%1,%2,%3}, {%4,%5,%6,%7}, {%8,%9}, {%0,%1,%2,%3};"                  \
      : "+f"(d[0]), "+f"(d[1]), "+f"(d[2]), "+f"(d[3])                         \
      : "r"(a[0]), "r"(a[1]), "r"(a[2]), "r"(a[3]), "r"(b[0]), "r"(b[1]))

// ----------------------------------------------------------------------------
// Router GEMM: h = x[M,K] @ Wr[K,N] + br, computed with 3xTF32 (fp32-accurate)
// CTA tile 128x128xBK16, 8 warps (4x2), warp tile 32x64 (2x8 m16n8 frags)
// ----------------------------------------------------------------------------
__global__ __launch_bounds__(256) void router_gemm(
    const float* __restrict__ x, const float* __restrict__ Wr,
    const float* __restrict__ br) {
  // padded smem: A stride 20 (frag loads conflict-free), B stride 136
  __shared__ __align__(16) float As_h[128][20];
  __shared__ __align__(16) float As_l[128][20];
  __shared__ __align__(16) float Bs_h[16][136];
  __shared__ __align__(16) float Bs_l[16][136];

  const int tid   = threadIdx.x;
  const int lane  = tid & 31;
  const int wid   = tid >> 5;
  const int warpM = wid & 3;   // 4 warps along M (32 rows each)
  const int warpN = wid >> 2;  // 2 warps along N (64 cols each)
  const int m0    = blockIdx.x * 128;
  const int g     = lane >> 2;  // groupID
  const int tg    = lane & 3;   // thread-in-group

  float acc[2][8][4];
#pragma unroll
  for (int mf = 0; mf < 2; ++mf)
#pragma unroll
    for (int nf = 0; nf < 8; ++nf)
#pragma unroll
      for (int j = 0; j < 4; ++j) acc[mf][nf][j] = 0.0f;

  const int ktiles = (K_DIM + 15) / 16;  // 593 (last tile has 8 valid k)

  for (int kt = 0; kt < ktiles; ++kt) {
    const int k0 = kt * 16;

    // ---- load A tile (128x16 fp32), split into tf32 hi/lo ----
#pragma unroll
    for (int i = 0; i < 2; ++i) {
      int q   = tid + i * 256;     // 0..511 float4 slots
      int row = q >> 2;            // 0..127
      int k4  = (q & 3) * 4;       // 0,4,8,12
      int gr  = m0 + row;
      int gk  = k0 + k4;
      float4 v = make_float4(0.f, 0.f, 0.f, 0.f);
      if (gr < M_ROWS && gk + 3 < K_DIM)
        v = *(const float4*)(x + (size_t)gr * K_DIM + gk);
      float h0 = __uint_as_float(f2tf32(v.x));
      float h1 = __uint_as_float(f2tf32(v.y));
      float h2 = __uint_as_float(f2tf32(v.z));
      float h3 = __uint_as_float(f2tf32(v.w));
      As_h[row][k4 + 0] = h0;
      As_h[row][k4 + 1] = h1;
      As_h[row][k4 + 2] = h2;
      As_h[row][k4 + 3] = h3;
      As_l[row][k4 + 0] = __uint_as_float(f2tf32(v.x - h0));
      As_l[row][k4 + 1] = __uint_as_float(f2tf32(v.y - h1));
      As_l[row][k4 + 2] = __uint_as_float(f2tf32(v.z - h2));
      As_l[row][k4 + 3] = __uint_as_float(f2tf32(v.w - h3));
    }

    // ---- load B tile (16x128 fp32), split into tf32 hi/lo ----
#pragma unroll
    for (int i = 0; i < 2; ++i) {
      int q  = tid + i * 256;  // 0..511 float4 slots
      int kr = q >> 5;         // 0..15
      int n4 = (q & 31) * 4;   // 0..124
      int gk = k0 + kr;
      float4 v = make_float4(0.f, 0.f, 0.f, 0.f);
      if (gk < K_DIM) v = *(const float4*)(Wr + (size_t)gk * N_DIM + n4);
      float h0 = __uint_as_float(f2tf32(v.x));
      float h1 = __uint_as_float(f2tf32(v.y));
      float h2 = __uint_as_float(f2tf32(v.z));
      float h3 = __uint_as_float(f2tf32(v.w));
      Bs_h[kr][n4 + 0] = h0;
      Bs_h[kr][n4 + 1] = h1;
      Bs_h[kr][n4 + 2] = h2;
      Bs_h[kr][n4 + 3] = h3;
      Bs_l[kr][n4 + 0] = __uint_as_float(f2tf32(v.x - h0));
      Bs_l[kr][n4 + 1] = __uint_as_float(f2tf32(v.y - h1));
      Bs_l[kr][n4 + 2] = __uint_as_float(f2tf32(v.z - h2));
      Bs_l[kr][n4 + 3] = __uint_as_float(f2tf32(v.w - h3));
    }
    __syncthreads();

    // ---- compute: 2 k8 steps ----
#pragma unroll
    for (int kk = 0; kk < 2; ++kk) {
      const int kb = kk * 8;
      uint32_t ah[2][4], al[2][4];
#pragma unroll
      for (int mf = 0; mf < 2; ++mf) {
        const int r = warpM * 32 + mf * 16;
        ah[mf][0] = __float_as_uint(As_h[r + g][kb + tg]);
        ah[mf][1] = __float_as_uint(As_h[r + g + 8][kb + tg]);
        ah[mf][2] = __float_as_uint(As_h[r + g][kb + tg + 4]);
        ah[mf][3] = __float_as_uint(As_h[r + g + 8][kb + tg + 4]);
        al[mf][0] = __float_as_uint(As_l[r + g][kb + tg]);
        al[mf][1] = __float_as_uint(As_l[r + g + 8][kb + tg]);
        al[mf][2] = __float_as_uint(As_l[r + g][kb + tg + 4]);
        al[mf][3] = __float_as_uint(As_l[r + g + 8][kb + tg + 4]);
      }
      uint32_t bh[8][2], bl[8][2];
#pragma unroll
      for (int nf = 0; nf < 8; ++nf) {
        const int c = warpN * 64 + nf * 8 + g;
        bh[nf][0] = __float_as_uint(Bs_h[kb + tg][c]);
        bh[nf][1] = __float_as_uint(Bs_h[kb + tg + 4][c]);
        bl[nf][0] = __float_as_uint(Bs_l[kb + tg][c]);
        bl[nf][1] = __float_as_uint(Bs_l[kb + tg + 4][c]);
      }
#pragma unroll
      for (int mf = 0; mf < 2; ++mf)
#pragma unroll
        for (int nf = 0; nf < 8; ++nf) {
          MMA_TF32(acc[mf][nf], ah[mf], bh[nf]);  // hi*hi
          MMA_TF32(acc[mf][nf], ah[mf], bl[nf]);  // hi*lo
          MMA_TF32(acc[mf][nf], al[mf], bh[nf]);  // lo*hi
        }
    }
    __syncthreads();
  }

  // ---- store h (+ bias) ----
#pragma unroll
  for (int mf = 0; mf < 2; ++mf) {
#pragma unroll
    for (int nf = 0; nf < 8; ++nf) {
      const int r0 = m0 + warpM * 32 + mf * 16 + g;
      const int c0 = warpN * 64 + nf * 8 + tg * 2;
      if (r0 < M_ROWS) {
        g_h[(size_t)r0 * N_DIM + c0]     = acc[mf][nf][0] + br[c0];
        g_h[(size_t)r0 * N_DIM + c0 + 1] = acc[mf][nf][1] + br[c0 + 1];
      }
      if (r0 + 8 < M_ROWS) {
        g_h[(size_t)(r0 + 8) * N_DIM + c0]     = acc[mf][nf][2] + br[c0];
        g_h[(size_t)(r0 + 8) * N_DIM + c0 + 1] = acc[mf][nf][3] + br[c0 + 1];
      }
    }
  }
}

// ----------------------------------------------------------------------------
// Epilogue: one warp per sample. top-2 gating -> experts (selected groups only)
// -> QKV -> 4x4 attention -> Wo at the selected expert -> weighted sum.
// ----------------------------------------------------------------------------
__global__ __launch_bounds__(256) void moe_epilogue(
    const float* __restrict__ We, const float* __restrict__ be,
    const float* __restrict__ Wq, const float* __restrict__ bq,
    const float* __restrict__ Wk, const float* __restrict__ bk,
    const float* __restrict__ Wv, const float* __restrict__ bvp,
    const float* __restrict__ Wo, const float* __restrict__ bo,
    float* __restrict__ out) {
  const int tid  = threadIdx.x;
  const int lane = tid & 31;
  const int w    = tid >> 5;
  const int n    = blockIdx.x * 8 + w;  // grid sized so n < M_ROWS always

  __shared__ __align__(16) float h_s[8][128];
  __shared__ float eo_s[8][32];
  __shared__ float qs[8][32];
  __shared__ float ks[8][32];
  __shared__ float vs[8][32];
  __shared__ float att_s[8][32];

  // 1) load h row, find top-2 (value desc, index asc on ties)
  float4 hv = *(const float4*)(g_h + (size_t)n * N_DIM + lane * 4);
  *(float4*)(&h_s[w][lane * 4]) = hv;
  float vals[4] = {hv.x, hv.y, hv.z, hv.w};

  float tv = vals[0];
  int   ti = lane * 4;
#pragma unroll
  for (int j = 1; j < 4; ++j)
    if (vals[j] > tv) { tv = vals[j]; ti = lane * 4 + j; }
#pragma unroll
  for (int off = 16; off > 0; off >>= 1) {
    float ov = __shfl_down_sync(0xffffffffu, tv, off);
    int   oi = __shfl_down_sync(0xffffffffu, ti, off);
    if (ov > tv || (ov == tv && oi < ti)) { tv = ov; ti = oi; }
  }
  const float v1 = __shfl_sync(0xffffffffu, tv, 0);
  const int   i1 = __shfl_sync(0xffffffffu, ti, 0);

  tv = -INFINITY;
  ti = 1 << 30;
#pragma unroll
  for (int j = 0; j < 4; ++j) {
    int idx = lane * 4 + j;
    if (idx != i1 && (vals[j] > tv || (vals[j] == tv && idx < ti))) {
      tv = vals[j];
      ti = idx;
    }
  }
#pragma unroll
  for (int off = 16; off > 0; off >>= 1) {
    float ov = __shfl_down_sync(0xffffffffu, tv, off);
    int   oi = __shfl_down_sync(0xffffffffu, ti, off);
    if (ov > tv || (ov == tv && oi < ti)) { tv = ov; ti = oi; }
  }
  const float v2 = __shfl_sync(0xffffffffu, tv, 0);
  const int   i2 = __shfl_sync(0xffffffffu, ti, 0);

  // gating weights (softmax over the 2 selected logits)
  const float e2w = expf(v2 - v1);
  const float rw1 = 1.0f / (1.0f + e2w);
  const float rw2 = 1.0f - rw1;

  const int g0 = i1 >> 4, f0 = i1 & 15;
  const int g1 = i2 >> 4, f1 = i2 & 15;

  __syncwarp();

  // 2) expert outputs for the (up to) 2 selected groups
  {
    const int sel = lane >> 4;
    const int e   = lane & 15;
    const int gg  = sel ? g1 : g0;
    const float* wrow = We + (size_t)(gg * NE + e) * 128;
    float acc = be[gg * NE + e];
#pragma unroll 8
    for (int k4 = 0; k4 < 32; ++k4) {
      float4 wv = ((const float4*)wrow)[k4];
      const float* hp = &h_s[w][k4 * 4];
      acc += hp[0] * wv.x + hp[1] * wv.y + hp[2] * wv.z + hp[3] * wv.w;
    }
    eo_s[w][lane] = acc;
  }
  __syncwarp();

  // 3) Q/K/V projections (per-group Linear(E->E), torch [out,in] layout)
  {
    const int sel = lane >> 4;
    const int f   = lane & 15;
    const int gg  = sel ? g1 : g0;
    const float* wq = Wq + (size_t)(gg * NE + f) * NE;
    const float* wk = Wk + (size_t)(gg * NE + f) * NE;
    const float* wv_ = Wv + (size_t)(gg * NE + f) * NE;
    float qa = bq[gg * NE + f];
    float ka = bk[gg * NE + f];
    float va = bvp[gg * NE + f];
#pragma unroll
    for (int e = 0; e < 16; ++e) {
      float eov = eo_s[w][sel * 16 + e];
      qa += eov * wq[e];
      ka += eov * wk[e];
      va += eov * wv_[e];
    }
    qs[w][lane] = qa;
    ks[w][lane] = ka;
    vs[w][lane] = va;
  }
  __syncwarp();

  // 4) 4x4 attention per selected group (head_dim axis is the seq axis)
  if (lane < 8) {
    const int sel  = lane >> 2;
    const int d    = lane & 3;
    const int base = sel * 16;
    float qv[4];
#pragma unroll
    for (int hh = 0; hh < 4; ++hh) qv[hh] = qs[w][base + hh * 4 + d];
    float sc[4];
#pragma unroll
    for (int e = 0; e < 4; ++e) {
      float s = 0.0f;
#pragma unroll
      for (int hh = 0; hh < 4; ++hh) s += qv[hh] * ks[w][base + hh * 4 + e];
      sc[e] = s * 0.5f;  // / sqrt(DH=4)
    }
    float mx = fmaxf(fmaxf(sc[0], sc[1]), fmaxf(sc[2], sc[3]));
    float ex[4], ssum = 0.0f;
#pragma unroll
    for (int e = 0; e < 4; ++e) {
      ex[e] = expf(sc[e] - mx);
      ssum += ex[e];
    }
    const float inv = 1.0f / ssum;
#pragma unroll
    for (int hh = 0; hh < 4; ++hh) {
      float a = 0.0f;
#pragma unroll
      for (int e = 0; e < 4; ++e) a += ex[e] * inv * vs[w][base + hh * 4 + e];
      att_s[w][base + hh * 4 + d] = a;  // att_flat[g, hh*4+d]
    }
  }
  __syncwarp();

  // 5) output projection at the selected expert index + gated combine
  {
    const int sel = lane & 1;
    const int gg  = sel ? g1 : g0;
    const int f   = sel ? f1 : f0;
    const float* wo = Wo + (size_t)(gg * NE + f) * NE;
    float o = bo[gg * NE + f];
#pragma unroll
    for (int e = 0; e < 16; ++e) o += att_s[w][sel * 16 + e] * wo[e];
    const float o0 = __shfl_sync(0xffffffffu, o, 0);
    const float o1 = __shfl_sync(0xffffffffu, o, 1);
    if (lane == 0) out[n] = rw1 * o0 + rw2 * o1;
  }
}

// ----------------------------------------------------------------------------
// launch
// ----------------------------------------------------------------------------
extern "C" void kernel_launch(void* const* d_in, const int* in_sizes, int n_in,
                              void* d_out, int out_size) {
  const float* x  = (const float*)d_in[0];
  const float* Wr = (const float*)d_in[1];
  const float* br = (const float*)d_in[2];
  const float* We = (const float*)d_in[3];
  const float* be = (const float*)d_in[4];
  const float* Wq = (const float*)d_in[5];
  const float* bq = (const float*)d_in[6];
  const float* Wk = (const float*)d_in[7];
  const float* bk = (const float*)d_in[8];
  const float* Wv = (const float*)d_in[9];
  const float* bv = (const float*)d_in[10];
  const float* Wo = (const float*)d_in[11];
  const float* bo = (const float*)d_in[12];
  float* out = (float*)d_out;

  router_gemm<<<(M_ROWS + 127) / 128, 256>>>(x, Wr, br);
  moe_epilogue<<<M_ROWS / 8, 256>>>(We, be, Wq, bq, Wk, bk, Wv, bv, Wo, bo,
                                    out);
}